// round 17
// baseline (speedup 1.0000x reference)
#include <cuda_runtime.h>
#include <cuda_bf16.h>

// KANStressPredictor: elementwise map over [B, T, 3] f32 strain.
// Group math (s0,s1,s2):
//   mean = s0+s1+1 ;  rad = sqrt((s0-s1)^2 + s2^2)
//   lam0 = mean-rad, lam1 = mean+rad    [eigenvalues of C = 2E+I]
//   lg_i = log2(lam_i) ;  L = lg0+lg1 = log2(det C)
//   out_i = exp2( ki0*0.5*lg_i - ki0*L/6 ) ;  out_2 = 0.5*ln2*ki1 * L
//
// R17: persistent warps + register software pipeline. R13's warp is
// one-shot: 3 LDGs, one long wait, then ~400cyc of smem/compute/store with
// ZERO loads outstanding (DRAM stuck ~65% across all variants; memcpy-class
// kernels reach ~85-90%). Here each warp loops over ~7 tiles and issues the
// NEXT tile's 3 LDG.128 before processing the current tile, keeping loads
// in flight continuously. No block barriers (syncwarp only); ~1 wave grid.

#define LN2_F 0.6931471805599453f

__device__ __forceinline__ float ex2_approx(float x) {
    float r;
    asm("ex2.approx.ftz.f32 %0, %1;" : "=f"(r) : "f"(x));
    return r;
}

__device__ __forceinline__ void kan_group(float s0, float s1, float s2,
                                          float ki0h, float ki0_6, float k1s,
                                          float& o0, float& o1, float& o2) {
    float mean = s0 + s1 + 1.0f;
    float diff = s0 - s1;
    float rad  = __fsqrt_rn(fmaf(diff, diff, s2 * s2));

    float lam0 = mean - rad;                   // rad < 0.3*mean: no cancellation
    float lam1 = mean + rad;
    float lg0  = __log2f(lam0);
    float lg1  = __log2f(lam1);
    float L    = lg0 + lg1;                    // log2(det)

    float base = ki0_6 * L;
    o0 = ex2_approx(fmaf(ki0h, lg0, -base));
    o1 = ex2_approx(fmaf(ki0h, lg1, -base));
    o2 = k1s * L;
}

// warp-tile = 96 float4 = 384 floats = 128 groups; 8 warps/block
#define WARPS_PER_BLOCK 8
#define GRID_BLOCKS 1184     // 148 SMs x 8 resident (12KB smem, <=42 regs)

__global__ void __launch_bounds__(256, 6)
kan_stress_persist_kernel(const float4* __restrict__ in, float4* __restrict__ out,
                          const float* __restrict__ ki0p, const float* __restrict__ ki1p,
                          long long n_wtiles) {
    __shared__ float4 s[WARPS_PER_BLOCK][96];

    int lane = threadIdx.x & 31;
    int wip  = threadIdx.x >> 5;
    long long w      = (long long)blockIdx.x * WARPS_PER_BLOCK + wip;
    long long stride = (long long)gridDim.x * WARPS_PER_BLOCK;

    float ki0 = __ldg(ki0p);
    float ki1 = __ldg(ki1p);
    float ki0h  = 0.5f * ki0;
    float ki0_6 = ki0 * (1.0f / 6.0f);
    float k1s   = 0.5f * LN2_F * ki1;

    float4* sw = s[wip];

    long long wt = w;
    if (wt >= n_wtiles) return;          // whole warp exits together

    // prologue: load first tile
    const float4* src = in + wt * 96;
    float4 r0 = src[lane];
    float4 r1 = src[lane + 32];
    float4 r2 = src[lane + 64];

    while (true) {
        long long nxt = wt + stride;

        // issue NEXT tile's loads before processing current (overlap DRAM
        // latency with the ~400cyc process phase below)
        float4 n0, n1, n2;
        bool have_next = (nxt < n_wtiles);
        if (have_next) {
            const float4* nsrc = in + nxt * 96;
            n0 = nsrc[lane];
            n1 = nsrc[lane + 32];
            n2 = nsrc[lane + 64];
        }

        // ---- process current tile (R13 structure, warp-private) ----
        sw[lane     ] = r0;
        sw[lane + 32] = r1;
        sw[lane + 64] = r2;
        __syncwarp();

        // stride-3 gather (LDS.128 stride 48B, conflict-free)
        float4 a = sw[3 * lane + 0];
        float4 b = sw[3 * lane + 1];
        float4 c = sw[3 * lane + 2];

        float4 ra, rb, rc;
        kan_group(a.x, a.y, a.z, ki0h, ki0_6, k1s, ra.x, ra.y, ra.z);
        kan_group(a.w, b.x, b.y, ki0h, ki0_6, k1s, ra.w, rb.x, rb.y);
        kan_group(b.z, b.w, c.x, ki0h, ki0_6, k1s, rb.z, rb.w, rc.x);
        kan_group(c.y, c.z, c.w, ki0h, ki0_6, k1s, rc.y, rc.z, rc.w);

        sw[3 * lane + 0] = ra;          // in-place: thread-private region
        sw[3 * lane + 1] = rb;
        sw[3 * lane + 2] = rc;
        __syncwarp();

        float4* dst = out + wt * 96;
        __stcs(&dst[lane     ], sw[lane     ]);
        __stcs(&dst[lane + 32], sw[lane + 32]);
        __stcs(&dst[lane + 64], sw[lane + 64]);

        if (!have_next) break;
        __syncwarp();                    // readers done before next STS
        r0 = n0; r1 = n1; r2 = n2;
        wt = nxt;
    }
}

// Scalar fallback for groups beyond full warp-tiles (defensive; unused for
// the benchmarked 4096x2048x3 shape: 25165824/384 = 65536 exact).
__global__ void kan_stress_tail_kernel(const float* __restrict__ in, float* __restrict__ out,
                                       const float* __restrict__ ki0p, const float* __restrict__ ki1p,
                                       long long g0, long long n_groups) {
    long long g = g0 + blockIdx.x * (long long)blockDim.x + threadIdx.x;
    if (g >= n_groups) return;

    float ki0 = __ldg(ki0p);
    float ki1 = __ldg(ki1p);
    float ki0h  = 0.5f * ki0;
    float ki0_6 = ki0 * (1.0f / 6.0f);
    float k1s   = 0.5f * LN2_F * ki1;

    float s0 = in[3 * g + 0];
    float s1 = in[3 * g + 1];
    float s2 = in[3 * g + 2];
    float o0, o1, o2;
    kan_group(s0, s1, s2, ki0h, ki0_6, k1s, o0, o1, o2);
    out[3 * g + 0] = o0;
    out[3 * g + 1] = o1;
    out[3 * g + 2] = o2;
}

extern "C" void kernel_launch(void* const* d_in, const int* in_sizes, int n_in,
                              void* d_out, int out_size) {
    const float* strain = (const float*)d_in[0];
    const float* ki0    = (const float*)d_in[1];
    const float* ki1    = (const float*)d_in[2];
    float* out          = (float*)d_out;

    long long total_floats = in_sizes[0];     // B*T*3
    long long n_groups = total_floats / 3;
    long long n_wtiles = total_floats / 384;  // 384 floats per warp-tile

    if (n_wtiles > 0) {
        long long need_blocks = (n_wtiles + WARPS_PER_BLOCK - 1) / WARPS_PER_BLOCK;
        int grid = (int)(need_blocks < GRID_BLOCKS ? need_blocks : GRID_BLOCKS);
        kan_stress_persist_kernel<<<grid, 256>>>(
            (const float4*)strain, (float4*)out, ki0, ki1, n_wtiles);
    }

    long long g0 = n_wtiles * 128;            // 128 groups per warp-tile
    if (g0 < n_groups) {
        long long rem = n_groups - g0;
        int block = 128;
        int grid = (int)((rem + block - 1) / block);
        kan_stress_tail_kernel<<<grid, block>>>(strain, out, ki0, ki1, g0, n_groups);
    }
}